// round 7
// baseline (speedup 1.0000x reference)
#include <cuda_runtime.h>
#include <math.h>

#define N_NODES 20000
#define N_EDGES 50000
#define C 64
#define NREL 32
#define MAXTILES 424                 // >= 50000/128 + 32
#define ORDER_CAP (MAXTILES * 128)   // 54272

// ---------------- scratch (no allocations allowed) ----------------
struct __align__(16) GScratch {
    int cnt_src[N_NODES];
    int cnt_dst[N_NODES];
    int hist[NREL];
    int cursor[NREL];
    int order[ORDER_CAP];            // stores e+1; 0 = empty/pad
};
__device__ GScratch G;
__device__ float g_inv[2][NREL];
__device__ int g_is64;

__device__ __forceinline__ int load_idx(const void* p, int i, int is64) {
    return is64 ? (int)((const long long*)p)[i] : ((const int*)p)[i];
}
__device__ __forceinline__ unsigned f2tf(float f) {
    unsigned u; asm("cvt.rna.tf32.f32 %0, %1;" : "=r"(u) : "f"(f)); return u;
}
__device__ __forceinline__ void mma_tf32(float* d,
    unsigned a0, unsigned a1, unsigned a2, unsigned a3,
    unsigned b0, unsigned b1)
{
    asm volatile(
        "mma.sync.aligned.m16n8k8.row.col.f32.tf32.tf32.f32 "
        "{%0,%1,%2,%3},{%4,%5,%6,%7},{%8,%9},{%0,%1,%2,%3};"
        : "+f"(d[0]), "+f"(d[1]), "+f"(d[2]), "+f"(d[3])
        : "r"(a0), "r"(a1), "r"(a2), "r"(a3), "r"(b0), "r"(b1));
}
__device__ __forceinline__ void ldsm4(unsigned& r0, unsigned& r1,
                                      unsigned& r2, unsigned& r3, unsigned addr)
{
    asm volatile("ldmatrix.sync.aligned.m8n8.x4.shared.b16 {%0,%1,%2,%3}, [%4];"
                 : "=r"(r0), "=r"(r1), "=r"(r2), "=r"(r3) : "r"(addr));
}
__device__ __forceinline__ void cpa16(unsigned dst, const void* src) {
    asm volatile("cp.async.ca.shared.global [%0], [%1], 16;"
                 :: "r"(dst), "l"(src) : "memory");
}
__device__ __forceinline__ void bulk_red_row(float* gdst, unsigned ssrc) {
    asm volatile(
        "cp.reduce.async.bulk.global.shared::cta.bulk_group.add.f32 [%0], [%1], 256;"
        :: "l"(gdst), "r"(ssrc) : "memory");
}
__device__ __forceinline__ void bulk_store_row(float* gdst, unsigned ssrc) {
    asm volatile(
        "cp.async.bulk.global.shared::cta.bulk_group [%0], [%1], 256;"
        :: "l"(gdst), "r"(ssrc) : "memory");
}
// swizzled index for [rows][64] arrays: element (m,k)
#define SWZ(m, k) ((m) * 64 + ((((k) >> 2) ^ ((m) & 7)) << 2) + ((k) & 3))
#define OSTRIDE 68                   // staging row stride (floats), conflict-free

// ---------------- prep ------------------------------------------------------
__global__ __launch_bounds__(256) void k_prep(
    const float* __restrict__ wf, const float* __restrict__ wb,
    const void* __restrict__ ei)
{
    int b = blockIdx.x, tid = threadIdx.x;
    if (b < 64) {
        __shared__ float red[256];
        int r = b & 31, tab = b >> 5;
        const float* w = (tab ? wb : wf) + (size_t)r * (C * C);
        float s = 0.f;
        for (int j = tid; j < C * C; j += 256) { float v = w[j]; s += v * v; }
        red[tid] = s; __syncthreads();
        for (int o = 128; o > 0; o >>= 1) {
            if (tid < o) red[tid] += red[tid + o];
            __syncthreads();
        }
        if (tid == 0) g_inv[tab][r] = 1.f / (sqrtf(red[0]) + 0.01f);
    } else if (b == 64) {
        if (tid < 32) {
            int hi = ((const int*)ei)[2 * tid + 1];
            unsigned ok = __ballot_sync(0xFFFFFFFFu, hi == 0);
            if (tid == 0) g_is64 = (ok == 0xFFFFFFFFu) ? 1 : 0;
        }
    } else {
        int i = (b - 65) * 256 + tid;
        const int n16 = (int)(sizeof(GScratch) / 16);
        if (i < n16) ((int4*)&G)[i] = make_int4(0, 0, 0, 0);
    }
}

// ---------------- count -----------------------------------------------------
__global__ __launch_bounds__(256) void k_count(
    const void* __restrict__ ei, const void* __restrict__ et)
{
    __shared__ int h[NREL];
    int tid = threadIdx.x;
    if (tid < NREL) h[tid] = 0;
    __syncthreads();
    int e = blockIdx.x * 256 + tid;
    int is64 = g_is64;
    if (e < N_EDGES) {
        atomicAdd(&G.cnt_src[load_idx(ei, e, is64)], 1);
        atomicAdd(&G.cnt_dst[load_idx(ei, N_EDGES + e, is64)], 1);
        atomicAdd(&h[load_idx(et, e, is64)], 1);
    }
    __syncthreads();
    if (tid < NREL && h[tid]) atomicAdd(&G.hist[tid], h[tid]);
}

// ====== tensor-core inner loop: 1xTF32 (rna-rounded in regs) ================
__device__ __forceinline__ void mma_main(
    unsigned sA, unsigned sBh, int lane, int warp, float d[8][4])
{
    int mA  = warp * 16 + (lane & 15);
    unsigned aconst = mA * 256u;
    unsigned ahx = (unsigned)(((lane >> 4) ^ (mA & 7)) & 15);
    int nr  = ((lane & 16) >> 1) + (lane & 7);
    unsigned bconst = nr * 256u;
    unsigned bhx = (unsigned)((((lane >> 3) & 1) ^ (lane & 7)) & 15);

    #pragma unroll
    for (int s8 = 0; s8 < 8; s8++) {
        unsigned kg = 2 * s8;
        unsigned a0u, a1u, a2u, a3u;
        ldsm4(a0u, a1u, a2u, a3u, sA + aconst + (((kg ^ ahx) & 15u) << 4));
        unsigned ah0 = f2tf(__uint_as_float(a0u));
        unsigned ah1 = f2tf(__uint_as_float(a1u));
        unsigned ah2 = f2tf(__uint_as_float(a2u));
        unsigned ah3 = f2tf(__uint_as_float(a3u));
        unsigned boff = ((kg ^ bhx) & 15u) << 4;
        #pragma unroll
        for (int jj = 0; jj < 4; jj++) {
            unsigned bh0, bh1, bh2, bh3;
            ldsm4(bh0, bh1, bh2, bh3, sBh + bconst + jj * 16u * 256u + boff);
            mma_tf32(d[2 * jj],     ah0, ah1, ah2, ah3, bh0, bh1);
            mma_tf32(d[2 * jj + 1], ah0, ah1, ah2, ah3, bh2, bh3);
        }
    }
}

// ---------------- scatter + linear term -------------------------------------
#define SCAT_BLOCKS 196
#define LIN_BLOCKS ((N_NODES + 127) / 128)
#define TC_SMEM_FLOATS (8192 + 4096)              // A raw 32KB + Bh 16KB
#define SCAT_SMEM_BYTES (TC_SMEM_FLOATS * 4)      // OutS (8704 fl) overlaps A+B

__global__ __launch_bounds__(256, 3) void k_scatlin(
    const void* __restrict__ et, const float* __restrict__ x,
    const float* __restrict__ lw, const float* __restrict__ lb,
    float* __restrict__ out)
{
    int tid = threadIdx.x;
    if (blockIdx.x < SCAT_BLOCKS) {
        __shared__ int obase[NREL];
        __shared__ int bcnt[NREL];
        __shared__ int gbase[NREL];
        if (tid < 32) {
            int nt = (G.hist[tid] + 127) >> 7;
            int a = nt;
            #pragma unroll
            for (int o = 1; o < 32; o <<= 1) {
                int v = __shfl_up_sync(0xFFFFFFFFu, a, o);
                if (tid >= o) a += v;
            }
            obase[tid] = (a - nt) * 128;
            bcnt[tid] = 0;
        }
        __syncthreads();
        int e = blockIdx.x * 256 + tid;
        int r = 0, my = 0, valid = (e < N_EDGES);
        if (valid) {
            r = load_idx(et, e, g_is64);
            my = atomicAdd(&bcnt[r], 1);
        }
        __syncthreads();
        if (tid < 32 && bcnt[tid]) gbase[tid] = atomicAdd(&G.cursor[tid], bcnt[tid]);
        __syncthreads();
        if (valid) G.order[obase[r] + gbase[r] + my] = e + 1;
        return;
    }

    extern __shared__ float sm[];
    float* Bth = sm + 8192;
    float* OutS = sm;                 // reuses A(+B head) after mma
    unsigned sbase = (unsigned)__cvta_generic_to_shared(sm);
    unsigned sA = sbase, sBh = sbase + 8192 * 4;

    int node0 = (blockIdx.x - SCAT_BLOCKS) * 128;

    {   // A = x rows (raw, cp.async into swizzled tile)
        int m = tid & 127, h = tid >> 7;
        int node = node0 + m;
        if (node >= N_NODES) node = 0;
        const float* xr = x + (size_t)node * C + h * 32;
        #pragma unroll
        for (int q = 0; q < 8; q++) {
            int pg = (h * 8 + q) ^ (m & 7);
            cpa16(sA + (unsigned)(m * 64 + pg * 4) * 4u, xr + q * 4);
        }
        asm volatile("cp.async.commit_group;" ::: "memory");
    }
    {   // B = lw (row n, col k) -> Bt[n][k] swizzled tf32
        const float4* w4 = (const float4*)lw;
        #pragma unroll
        for (int q = 0; q < 4; q++) {
            int i4 = tid + 256 * q;
            float4 v = w4[i4];
            int n = i4 >> 4;
            int pg = (i4 & 15) ^ (n & 7);
            float4 hi;
            hi.x = __uint_as_float(f2tf(v.x));
            hi.y = __uint_as_float(f2tf(v.y));
            hi.z = __uint_as_float(f2tf(v.z));
            hi.w = __uint_as_float(f2tf(v.w));
            *(float4*)&Bth[n * 64 + pg * 4] = hi;
        }
    }
    asm volatile("cp.async.wait_group 0;" ::: "memory");
    __syncthreads();

    int lane = tid & 31, w = tid >> 5;
    float d[8][4] = {};
    mma_main(sA, sBh, lane, w, d);
    __syncthreads();                  // all LDSM reads done before staging

    // stage (+bias) into OutS, shfl-paired v4
    int gid = lane >> 2, tig = lane & 3;
    int r0 = w * 16 + gid, r1 = r0 + 8;
    bool lowlane = !(tig & 1);
    #pragma unroll
    for (int j = 0; j < 8; j++) {
        float a0 = d[j][0], a1 = d[j][1], b0 = d[j][2], b1 = d[j][3];
        float a2 = __shfl_xor_sync(0xFFFFFFFFu, a0, 1);
        float a3 = __shfl_xor_sync(0xFFFFFFFFu, a1, 1);
        float b2 = __shfl_xor_sync(0xFFFFFFFFu, b0, 1);
        float b3 = __shfl_xor_sync(0xFFFFFFFFu, b1, 1);
        if (lowlane) {
            int n = j * 8 + 2 * tig;
            float4 bias = *(const float4*)(lb + n);
            *(float4*)&OutS[r0 * OSTRIDE + n] =
                make_float4(a0 + bias.x, a1 + bias.y, a2 + bias.z, a3 + bias.w);
            *(float4*)&OutS[r1 * OSTRIDE + n] =
                make_float4(b0 + bias.x, b1 + bias.y, b2 + bias.z, b3 + bias.w);
        }
    }
    __syncthreads();
    asm volatile("fence.proxy.async.shared::cta;" ::: "memory");

    if (tid < 128 && node0 + tid < N_NODES)
        bulk_store_row(out + (size_t)(node0 + tid) * C,
                       sbase + (unsigned)(tid * OSTRIDE) * 4u);
    asm volatile("cp.async.bulk.commit_group;" ::: "memory");
    asm volatile("cp.async.bulk.wait_group 0;" ::: "memory");
}

// ---------------- conv (persistent, TMA bulk-reduce scatter) ----------------
#define CONV_SMEM_FLOATS (TC_SMEM_FLOATS + 128 * 3 + 33)
#define CONV_SMEM_BYTES (CONV_SMEM_FLOATS * 4)
#define CONV_GRID (148 * 3)

__global__ __launch_bounds__(256, 3) void k_conv(
    const float* __restrict__ x, const void* __restrict__ ei,
    const float* __restrict__ wf, const float* __restrict__ wb,
    float* __restrict__ out)
{
    extern __shared__ float sm[];
    float* Bth = sm + 8192;
    float* OutS = sm;                 // staged messages; overlaps A + B head
    int*   Ss  = (int*)(sm + 12288);
    int*   Ds  = Ss + 128;
    float* Cs  = (float*)(Ds + 128);
    int*   Tst = (int*)(Cs + 128);
    unsigned sbase = (unsigned)__cvta_generic_to_shared(sm);
    unsigned sA = sbase, sBh = sbase + 8192 * 4;

    int tid = threadIdx.x;
    int is64 = g_is64;

    if (tid < 32) {
        int nt = (G.hist[tid] + 127) >> 7;
        int a = nt;
        #pragma unroll
        for (int o = 1; o < 32; o <<= 1) {
            int v = __shfl_up_sync(0xFFFFFFFFu, a, o);
            if (tid >= o) a += v;
        }
        Tst[tid] = a - nt;
        if (tid == 31) Tst[32] = a;
    }
    __syncthreads();
    int ntiles = Tst[32];

    for (int work = blockIdx.x; work < 2 * ntiles; work += CONV_GRID) {
        int dir = work >= ntiles;
        int tile = work - dir * ntiles;

        int r = 0;
        while (r < 31 && Tst[r + 1] <= tile) r++;
        float inv = g_inv[dir][r];

        // previous iteration's bulk-reduce must have READ OutS before we
        // overwrite the A/B regions below
        asm volatile("cp.async.bulk.wait_group.read 0;" ::: "memory");
        __syncthreads();

        if (tid < 128) {
            int ep = G.order[tile * 128 + tid];
            int s = 0, d = -1; float c = 0.f;
            if (ep > 0) {
                int e = ep - 1;
                int a = load_idx(ei, e, is64);
                int b2 = load_idx(ei, N_EDGES + e, is64);
                if (dir) { int t = a; a = b2; b2 = t; }
                s = a; d = b2;
                int cnt = dir ? G.cnt_dst[s] : G.cnt_src[s];
                c = inv / (float)(cnt + 1);
            }
            Ss[tid] = s; Ds[tid] = d; Cs[tid] = c;
        }
        __syncthreads();

        {   // A rows (raw x) via cp.async
            int m = tid & 127, h = tid >> 7;
            const float* xr = x + (size_t)Ss[m] * C + h * 32;
            #pragma unroll
            for (int q = 0; q < 8; q++) {
                int pg = (h * 8 + q) ^ (m & 7);
                cpa16(sA + (unsigned)(m * 64 + pg * 4) * 4u, xr + q * 4);
            }
            asm volatile("cp.async.commit_group;" ::: "memory");
        }
        {   // B = W_r ([k][n] gmem) -> Bt[n][k] swizzled tf32
            const float4* w4 = (const float4*)((dir ? wb : wf) + (size_t)r * (C * C));
            #pragma unroll
            for (int q = 0; q < 4; q++) {
                int i4 = tid + 256 * q;
                float4 v = w4[i4];
                int k = i4 >> 4;
                int n0 = (i4 & 15) * 4;
                float f[4] = {v.x, v.y, v.z, v.w};
                #pragma unroll
                for (int i = 0; i < 4; i++)
                    Bth[SWZ(n0 + i, k)] = __uint_as_float(f2tf(f[i]));
            }
        }
        asm volatile("cp.async.wait_group 0;" ::: "memory");
        __syncthreads();

        int lane = tid & 31, w = tid >> 5;
        float d[8][4] = {};
        mma_main(sA, sBh, lane, w, d);
        __syncthreads();              // all LDSM reads done before staging

        // stage scaled messages into OutS (shfl-paired v4 STS)
        int gid = lane >> 2, tig = lane & 3;
        int r0 = w * 16 + gid, r1 = r0 + 8;
        float c0 = Cs[r0], c1 = Cs[r1];
        bool lowlane = !(tig & 1);
        #pragma unroll
        for (int j = 0; j < 8; j++) {
            float a0 = d[j][0] * c0, a1 = d[j][1] * c0;
            float b0 = d[j][2] * c1, b1 = d[j][3] * c1;
            float a2 = __shfl_xor_sync(0xFFFFFFFFu, a0, 1);
            float a3 = __shfl_xor_sync(0xFFFFFFFFu, a1, 1);
            float b2 = __shfl_xor_sync(0xFFFFFFFFu, b0, 1);
            float b3 = __shfl_xor_sync(0xFFFFFFFFu, b1, 1);
            if (lowlane) {
                int n = j * 8 + 2 * tig;
                *(float4*)&OutS[r0 * OSTRIDE + n] = make_float4(a0, a1, a2, a3);
                *(float4*)&OutS[r1 * OSTRIDE + n] = make_float4(b0, b1, b2, b3);
            }
        }
        __syncthreads();
        asm volatile("fence.proxy.async.shared::cta;" ::: "memory");

        // one TMA bulk atomic-add per edge row
        if (tid < 128) {
            int dsti = Ds[tid];
            if (dsti >= 0)
                bulk_red_row(out + (size_t)dsti * C,
                             sbase + (unsigned)(tid * OSTRIDE) * 4u);
        }
        asm volatile("cp.async.bulk.commit_group;" ::: "memory");
    }
    asm volatile("cp.async.bulk.wait_group 0;" ::: "memory");
}

// ---------------- launch ----------------
extern "C" void kernel_launch(void* const* d_in, const int* in_sizes, int n_in,
                              void* d_out, int out_size)
{
    const float* x  = (const float*)d_in[0];
    const void*  ei = d_in[1];
    const void*  et = d_in[2];
    const float* wf = (const float*)d_in[3];
    const float* wb = (const float*)d_in[4];
    const float* lw = (const float*)d_in[5];
    const float* lb = (const float*)d_in[6];
    float* out = (float*)d_out;

    cudaFuncSetAttribute(k_conv, cudaFuncAttributeMaxDynamicSharedMemorySize,
                         CONV_SMEM_BYTES);
    cudaFuncSetAttribute(k_scatlin, cudaFuncAttributeMaxDynamicSharedMemorySize,
                         SCAT_SMEM_BYTES);

    const int zero_blocks = (int)((sizeof(GScratch) / 16 + 255) / 256);
    k_prep<<<64 + 1 + zero_blocks, 256>>>(wf, wb, ei);
    k_count<<<(N_EDGES + 255) / 256, 256>>>(ei, et);
    k_scatlin<<<SCAT_BLOCKS + LIN_BLOCKS, 256, SCAT_SMEM_BYTES>>>(et, x, lw, lb, out);
    k_conv<<<CONV_GRID, 256, CONV_SMEM_BYTES>>>(x, ei, wf, wb, out);
}